// round 3
// baseline (speedup 1.0000x reference)
#include <cuda_runtime.h>
#include <cuda_bf16.h>

#define NN 100000
#define EE 1600000
#define GG 64
#define NB ((NN + 255) / 256)   // 391 scan blocks

// ---------------- device scratch ----------------
__device__ float g_hp0[NN * 8];
__device__ float g_hp1[NN * 16];
__device__ float g_hp2[NN * 32];
__device__ float g_hp3[NN * 64];
__device__ int   g_csr[EE];
__device__ int   g_rowptr[NN];
__device__ int   g_cnt[NN];
__device__ int   g_deg[NN];        // in-degree WITHOUT self loop
__device__ float g_dinv[NN];
__device__ int   g_bsum[NB];
__device__ float g_psum[GG * 128];
__device__ int   g_pcnt[GG];

__device__ __forceinline__ void red_add_v4(float* p, float4 v) {
    asm volatile("red.global.add.v4.f32 [%0], {%1,%2,%3,%4};"
                 :: "l"(p), "f"(v.x), "f"(v.y), "f"(v.z), "f"(v.w)
                 : "memory");
}

// ---------------- init / degree ----------------
__global__ void k_zero() {
    int i = blockIdx.x * blockDim.x + threadIdx.x;
    if (i < NN) g_deg[i] = 0;
    if (i < GG * 128) g_psum[i] = 0.0f;
    if (i < GG) g_pcnt[i] = 0;
}
__global__ void k_deg_count(const int* __restrict__ dst) {
    int e = blockIdx.x * blockDim.x + threadIdx.x;
    if (e < EE) atomicAdd(&g_deg[dst[e]], 1);
}
// dinv + graph counts + prescaled layer-1 features (fused)
__global__ void k_dinv_prep(const int* __restrict__ batch, const float* __restrict__ x) {
    int n = blockIdx.x * blockDim.x + threadIdx.x;
    if (n >= NN) return;
    float d = rsqrtf((float)(g_deg[n] + 1));
    g_dinv[n] = d;
    atomicAdd(&g_pcnt[batch[n]], 1);
    float4 v0 = reinterpret_cast<const float4*>(x)[n * 2];
    float4 v1 = reinterpret_cast<const float4*>(x)[n * 2 + 1];
    reinterpret_cast<float4*>(g_hp0)[n * 2] =
        make_float4(v0.x * d, v0.y * d, v0.z * d, v0.w * d);
    reinterpret_cast<float4*>(g_hp0)[n * 2 + 1] =
        make_float4(v1.x * d, v1.y * d, v1.z * d, v1.w * d);
}

// ---------------- exclusive scan of g_deg -> g_rowptr ----------------
__global__ void k_scan1() {
    int t = threadIdx.x;
    int i = blockIdx.x * 256 + t;
    int v = (i < NN) ? g_deg[i] : 0;
    int lane = t & 31, w = t >> 5;
    int x = v;
#pragma unroll
    for (int d = 1; d < 32; d <<= 1) {
        int y = __shfl_up_sync(0xffffffffu, x, d);
        if (lane >= d) x += y;
    }
    __shared__ int ws[8];
    if (lane == 31) ws[w] = x;
    __syncthreads();
    if (w == 0) {
        int y = (lane < 8) ? ws[lane] : 0;
#pragma unroll
        for (int d = 1; d < 8; d <<= 1) {
            int z = __shfl_up_sync(0xffffffffu, y, d);
            if (lane >= d) y += z;
        }
        if (lane < 8) ws[lane] = y;
    }
    __syncthreads();
    int base = (w > 0) ? ws[w - 1] : 0;
    int incl = base + x;
    if (i < NN) g_rowptr[i] = incl - v;
    if (t == 255) g_bsum[blockIdx.x] = incl;
}
__global__ void k_scan2() {
    int t = threadIdx.x;                       // 512 threads
    int v = (t < NB) ? g_bsum[t] : 0;
    int lane = t & 31, w = t >> 5;
    int x = v;
#pragma unroll
    for (int d = 1; d < 32; d <<= 1) {
        int y = __shfl_up_sync(0xffffffffu, x, d);
        if (lane >= d) x += y;
    }
    __shared__ int ws[16];
    if (lane == 31) ws[w] = x;
    __syncthreads();
    if (w == 0) {
        int y = (lane < 16) ? ws[lane] : 0;
#pragma unroll
        for (int d = 1; d < 16; d <<= 1) {
            int z = __shfl_up_sync(0xffffffffu, y, d);
            if (lane >= d) y += z;
        }
        if (lane < 16) ws[lane] = y;
    }
    __syncthreads();
    int base = (w > 0) ? ws[w - 1] : 0;
    if (t < NB) g_bsum[t] = base + x - v;
}
__global__ void k_scan3() {
    int i = blockIdx.x * blockDim.x + threadIdx.x;
    if (i < NN) {
        int r = g_rowptr[i] + g_bsum[i >> 8];
        g_rowptr[i] = r;
        g_cnt[i] = r;
    }
}
__global__ void k_fill(const int* __restrict__ src, const int* __restrict__ dst) {
    int e = blockIdx.x * blockDim.x + threadIdx.x;
    if (e < EE) {
        int pos = atomicAdd(&g_cnt[dst[e]], 1);
        g_csr[pos] = src[e];
    }
}

// ---------------- fused layers ----------------
__device__ __forceinline__ const float* hp_in_of(int layer) {
    switch (layer) { case 1: return g_hp0; case 2: return g_hp1;
                     case 3: return g_hp2; default: return g_hp3; }
}
__device__ __forceinline__ float* hp_out_of(int layer) {
    switch (layer) { case 1: return g_hp1; case 2: return g_hp2;
                     default: return g_hp3; }
}

// Layers 1-3: WHOLE WARP per node. Lanes = EG edge-groups x L feature-lanes.
template<int LYR, int FIN, int FOUT>
__global__ void __launch_bounds__(256)
k_layer_coop(const float* __restrict__ W, const float* __restrict__ b,
             const float* __restrict__ aP)
{
    constexpr int L  = FIN / 2;           // feature lanes (float2 each)
    constexpr int EG = 32 / L;            // edge groups
    __shared__ alignas(16) float Ws[FIN * FOUT];
    __shared__ float bs[FOUT];
    for (int i = threadIdx.x; i < FIN * FOUT; i += blockDim.x) Ws[i] = W[i];
    for (int i = threadIdx.x; i < FOUT; i += blockDim.x) bs[i] = b[i];
    __syncthreads();
    float a = __ldg(aP);

    int warp = threadIdx.x >> 5, lane = threadIdx.x & 31;
    int node = blockIdx.x * 8 + warp;
    if (node >= NN) return;
    int sub = lane % L;                   // which float2 of the row
    int eg  = lane / L;                   // which edge group

    const float2* __restrict__ hp2 = reinterpret_cast<const float2*>(hp_in_of(LYR));

    float2 acc = make_float2(0.f, 0.f);
    if (eg == 0) acc = __ldg(&hp2[(size_t)node * L + sub]);   // self loop
    int e0  = __ldg(&g_rowptr[node]);
    int deg = __ldg(&g_deg[node]);

    int idx = eg;
    // unroll-2 over this group's strided edges
    for (; idx + EG < deg; idx += 2 * EG) {
        int s0 = __ldg(g_csr + e0 + idx);
        int s1 = __ldg(g_csr + e0 + idx + EG);
        float2 v0 = __ldg(&hp2[(size_t)s0 * L + sub]);
        float2 v1 = __ldg(&hp2[(size_t)s1 * L + sub]);
        acc.x += v0.x + v1.x;
        acc.y += v0.y + v1.y;
    }
    if (idx < deg) {
        int s = __ldg(g_csr + e0 + idx);
        float2 v = __ldg(&hp2[(size_t)s * L + sub]);
        acc.x += v.x; acc.y += v.y;
    }
    // butterfly-combine edge groups (lanes with equal sub)
#pragma unroll
    for (int off = 16; off >= L; off >>= 1) {
        acc.x += __shfl_xor_sync(0xffffffffu, acc.x, off);
        acc.y += __shfl_xor_sync(0xffffffffu, acc.y, off);
    }
    float dv = __ldg(&g_dinv[node]);
    acc.x *= dv; acc.y *= dv;   // replicated across all EG groups now

    // matmul: each lane computes outputs o = lane + 32*j
    constexpr int OPL = (FOUT + 31) / 32;
    float r[OPL];
#pragma unroll
    for (int j = 0; j < OPL; j++) {
        int o = lane + 32 * j;
        r[j] = (o < FOUT) ? bs[o] : 0.0f;
    }
#pragma unroll
    for (int k2 = 0; k2 < L; k2++) {
        float hx = __shfl_sync(0xffffffffu, acc.x, k2);
        float hy = __shfl_sync(0xffffffffu, acc.y, k2);
#pragma unroll
        for (int j = 0; j < OPL; j++) {
            int o = lane + 32 * j;
            if (o < FOUT)
                r[j] += hx * Ws[(2 * k2) * FOUT + o] + hy * Ws[(2 * k2 + 1) * FOUT + o];
        }
    }
    float* hp_out = hp_out_of(LYR);
#pragma unroll
    for (int j = 0; j < OPL; j++) {
        int o = lane + 32 * j;
        if (o < FOUT) {
            float v = r[j];
            v = (v >= 0.f) ? v : a * v;          // prelu
            hp_out[(size_t)node * FOUT + o] = v * dv;  // prescale for next layer
        }
    }
}

// Layer 4 (Fin=64 -> 128, no prelu) fused with mean-pool numerator.
__global__ void __launch_bounds__(256)
k_layer4(const float* __restrict__ W, const float* __restrict__ b,
         const int* __restrict__ batch)
{
    __shared__ alignas(16) float Ws[64 * 128];
    __shared__ float bs[128];
    for (int i = threadIdx.x; i < 64 * 128; i += blockDim.x) Ws[i] = W[i];
    for (int i = threadIdx.x; i < 128; i += blockDim.x) bs[i] = b[i];
    __syncthreads();

    int warp = threadIdx.x >> 5, lane = threadIdx.x & 31;
    int node = blockIdx.x * 8 + warp;
    if (node >= NN) return;

    const float2* __restrict__ hp2 = reinterpret_cast<const float2*>(g_hp3);
    float2 acc = __ldg(&hp2[(size_t)node * 32 + lane]);   // self loop
    int e = __ldg(&g_rowptr[node]);
    int rem = __ldg(&g_deg[node]);
    for (; rem >= 4; rem -= 4, e += 4) {
        int s0 = __ldg(g_csr + e), s1 = __ldg(g_csr + e + 1);
        int s2 = __ldg(g_csr + e + 2), s3 = __ldg(g_csr + e + 3);
        float2 v0 = __ldg(&hp2[(size_t)s0 * 32 + lane]);
        float2 v1 = __ldg(&hp2[(size_t)s1 * 32 + lane]);
        float2 v2 = __ldg(&hp2[(size_t)s2 * 32 + lane]);
        float2 v3 = __ldg(&hp2[(size_t)s3 * 32 + lane]);
        acc.x += (v0.x + v1.x) + (v2.x + v3.x);
        acc.y += (v0.y + v1.y) + (v2.y + v3.y);
    }
    for (; rem > 0; rem--, e++) {
        int s = __ldg(g_csr + e);
        float2 v = __ldg(&hp2[(size_t)s * 32 + lane]);
        acc.x += v.x; acc.y += v.y;
    }
    float dv = __ldg(&g_dinv[node]);
    acc.x *= dv; acc.y *= dv;

    float r0 = bs[4 * lane], r1 = bs[4 * lane + 1];
    float r2 = bs[4 * lane + 2], r3 = bs[4 * lane + 3];
#pragma unroll
    for (int k2 = 0; k2 < 32; k2++) {
        float hx = __shfl_sync(0xffffffffu, acc.x, k2);
        float hy = __shfl_sync(0xffffffffu, acc.y, k2);
        float4 wa = *reinterpret_cast<const float4*>(&Ws[(2 * k2) * 128 + 4 * lane]);
        float4 wb = *reinterpret_cast<const float4*>(&Ws[(2 * k2 + 1) * 128 + 4 * lane]);
        r0 += hx * wa.x + hy * wb.x;
        r1 += hx * wa.y + hy * wb.y;
        r2 += hx * wa.z + hy * wb.z;
        r3 += hx * wa.w + hy * wb.w;
    }
    int g = __ldg(&batch[node]);
    red_add_v4(&g_psum[g * 128 + 4 * lane], make_float4(r0, r1, r2, r3));
}

// ---------------- head ----------------
__global__ void k_final(const float* __restrict__ Wlin, const float* __restrict__ blin,
                        float* __restrict__ out) {
    int t = threadIdx.x;            // 64 graphs x 4 classes
    int g = t >> 2;
    int cls = t & 3;
    float inv = 1.0f / fmaxf((float)g_pcnt[g], 1.0f);
    float acc = blin[cls];
#pragma unroll 8
    for (int k = 0; k < 128; k++)
        acc += g_psum[g * 128 + k] * inv * Wlin[k * 4 + cls];
    out[g * 4 + cls] = acc;
}

// ---------------- launch ----------------
extern "C" void kernel_launch(void* const* d_in, const int* in_sizes, int n_in,
                              void* d_out, int out_size) {
    const float* x    = (const float*)d_in[0];
    const int*   es   = (const int*)d_in[1];
    const int*   ed   = (const int*)d_in[2];
    const int*   bt   = (const int*)d_in[3];
    const float* W1   = (const float*)d_in[4];
    const float* b1   = (const float*)d_in[5];
    const float* W2   = (const float*)d_in[6];
    const float* b2   = (const float*)d_in[7];
    const float* W3   = (const float*)d_in[8];
    const float* b3   = (const float*)d_in[9];
    const float* W4   = (const float*)d_in[10];
    const float* b4   = (const float*)d_in[11];
    const float* a1   = (const float*)d_in[12];
    const float* a2   = (const float*)d_in[13];
    const float* a3   = (const float*)d_in[14];
    const float* Wlin = (const float*)d_in[15];
    const float* blin = (const float*)d_in[16];

    const int B = 256;
    auto gr = [](long long n, int b) { return (unsigned)((n + b - 1) / b); };

    k_zero<<<gr(NN, B), B>>>();
    k_deg_count<<<gr(EE, B), B>>>(ed);
    k_dinv_prep<<<gr(NN, B), B>>>(bt, x);
    k_scan1<<<NB, 256>>>();
    k_scan2<<<1, 512>>>();
    k_scan3<<<gr(NN, B), B>>>();
    k_fill<<<gr(EE, B), B>>>(es, ed);

    // layers 1-3: warp-cooperative (1 node / warp, 8 warps / block)
    k_layer_coop<1, 8, 16><<<gr(NN, 8), B>>>(W1, b1, a1);
    k_layer_coop<2, 16, 32><<<gr(NN, 8), B>>>(W2, b2, a2);
    k_layer_coop<3, 32, 64><<<gr(NN, 8), B>>>(W3, b3, a3);
    // layer 4: fused with pool numerator
    k_layer4<<<gr(NN, 8), B>>>(W4, b4, bt);

    k_final<<<1, 256>>>(Wlin, blin, (float*)d_out);
}

// round 4
// speedup vs baseline: 2.0809x; 2.0809x over previous
#include <cuda_runtime.h>
#include <cuda_bf16.h>

#define NN 100000
#define EE 1600000
#define GG 64
#define NB ((NN + 255) / 256)   // 391 scan blocks

// ---------------- device scratch ----------------
__device__ float g_hp0[NN * 8];
__device__ float g_hp1[NN * 16];
__device__ float g_hp2[NN * 32];
__device__ float g_hp3[NN * 64];
__device__ int   g_csr[EE];
__device__ int   g_rowptr[NN];
__device__ int   g_cnt[NN];
__device__ int   g_deg[NN];        // in-degree WITHOUT self loop
__device__ float g_dinv[NN];
__device__ int   g_bsum[NB];
__device__ float g_psum[GG * 64];  // pooled pre-W4 sums
__device__ int   g_pcnt[GG];
__device__ float g_Wf[64 * 4];     // W4 @ Wlin
__device__ float g_bf[4];          // b4 @ Wlin + blin

__device__ __forceinline__ void red_add_v2(float* p, float2 v) {
    asm volatile("red.global.add.v2.f32 [%0], {%1,%2};"
                 :: "l"(p), "f"(v.x), "f"(v.y) : "memory");
}

// ---------------- init / degree ----------------
__global__ void k_zero() {
    int i = blockIdx.x * blockDim.x + threadIdx.x;
    if (i < NN) g_deg[i] = 0;
    if (i < GG * 64) g_psum[i] = 0.0f;
    if (i < GG) g_pcnt[i] = 0;
}
__global__ void k_deg_count(const int* __restrict__ dst) {
    int e = blockIdx.x * blockDim.x + threadIdx.x;
    if (e < EE) atomicAdd(&g_deg[dst[e]], 1);
}
// dinv + graph counts + prescaled layer-1 features (fused)
__global__ void k_dinv_prep(const int* __restrict__ batch, const float* __restrict__ x) {
    int n = blockIdx.x * blockDim.x + threadIdx.x;
    if (n >= NN) return;
    float d = rsqrtf((float)(g_deg[n] + 1));
    g_dinv[n] = d;
    atomicAdd(&g_pcnt[batch[n]], 1);
    float4 v0 = reinterpret_cast<const float4*>(x)[n * 2];
    float4 v1 = reinterpret_cast<const float4*>(x)[n * 2 + 1];
    reinterpret_cast<float4*>(g_hp0)[n * 2] =
        make_float4(v0.x * d, v0.y * d, v0.z * d, v0.w * d);
    reinterpret_cast<float4*>(g_hp0)[n * 2 + 1] =
        make_float4(v1.x * d, v1.y * d, v1.z * d, v1.w * d);
}
// fused head weights: Wf = W4 @ Wlin  [64,4], bf = b4 @ Wlin + blin
__global__ void k_fusew(const float* __restrict__ W4, const float* __restrict__ b4,
                        const float* __restrict__ Wlin, const float* __restrict__ blin) {
    int t = threadIdx.x;           // 256 = 64 rows x 4 cols
    int k = t >> 2, c = t & 3;
    float acc = 0.0f;
#pragma unroll 8
    for (int j = 0; j < 128; j++)
        acc += W4[k * 128 + j] * Wlin[j * 4 + c];
    g_Wf[k * 4 + c] = acc;
    if (k == 0) {
        float bb = blin[c];
        for (int j = 0; j < 128; j++) bb += b4[j] * Wlin[j * 4 + c];
        g_bf[c] = bb;
    }
}

// ---------------- exclusive scan of g_deg -> g_rowptr ----------------
__global__ void k_scan1() {
    int t = threadIdx.x;
    int i = blockIdx.x * 256 + t;
    int v = (i < NN) ? g_deg[i] : 0;
    int lane = t & 31, w = t >> 5;
    int x = v;
#pragma unroll
    for (int d = 1; d < 32; d <<= 1) {
        int y = __shfl_up_sync(0xffffffffu, x, d);
        if (lane >= d) x += y;
    }
    __shared__ int ws[8];
    if (lane == 31) ws[w] = x;
    __syncthreads();
    if (w == 0) {
        int y = (lane < 8) ? ws[lane] : 0;
#pragma unroll
        for (int d = 1; d < 8; d <<= 1) {
            int z = __shfl_up_sync(0xffffffffu, y, d);
            if (lane >= d) y += z;
        }
        if (lane < 8) ws[lane] = y;
    }
    __syncthreads();
    int base = (w > 0) ? ws[w - 1] : 0;
    int incl = base + x;
    if (i < NN) g_rowptr[i] = incl - v;
    if (t == 255) g_bsum[blockIdx.x] = incl;
}
__global__ void k_scan2() {
    int t = threadIdx.x;                       // 512 threads
    int v = (t < NB) ? g_bsum[t] : 0;
    int lane = t & 31, w = t >> 5;
    int x = v;
#pragma unroll
    for (int d = 1; d < 32; d <<= 1) {
        int y = __shfl_up_sync(0xffffffffu, x, d);
        if (lane >= d) x += y;
    }
    __shared__ int ws[16];
    if (lane == 31) ws[w] = x;
    __syncthreads();
    if (w == 0) {
        int y = (lane < 16) ? ws[lane] : 0;
#pragma unroll
        for (int d = 1; d < 16; d <<= 1) {
            int z = __shfl_up_sync(0xffffffffu, y, d);
            if (lane >= d) y += z;
        }
        if (lane < 16) ws[lane] = y;
    }
    __syncthreads();
    int base = (w > 0) ? ws[w - 1] : 0;
    if (t < NB) g_bsum[t] = base + x - v;
}
__global__ void k_scan3() {
    int i = blockIdx.x * blockDim.x + threadIdx.x;
    if (i < NN) {
        int r = g_rowptr[i] + g_bsum[i >> 8];
        g_rowptr[i] = r;
        g_cnt[i] = r;
    }
}
__global__ void k_fill(const int* __restrict__ src, const int* __restrict__ dst) {
    int e = blockIdx.x * blockDim.x + threadIdx.x;
    if (e < EE) {
        int pos = atomicAdd(&g_cnt[dst[e]], 1);
        g_csr[pos] = src[e];
    }
}

// ---------------- fused layers 1-3 (R2 structure, deeper unroll) ----------------
__device__ __forceinline__ const float* hp_in_of(int layer) {
    switch (layer) { case 1: return g_hp0; case 2: return g_hp1;
                     default: return g_hp2; }
}
__device__ __forceinline__ float* hp_out_of(int layer) {
    switch (layer) { case 1: return g_hp1; case 2: return g_hp2;
                     default: return g_hp3; }
}

template<int LYR, int FIN, int FOUT>
__global__ void __launch_bounds__(256)
k_layer(const float* __restrict__ W, const float* __restrict__ b,
        const float* __restrict__ aP)
{
    constexpr int L = FIN / 2;            // lanes per node
    constexpr int NPW = 32 / L;           // nodes per warp
    static_assert(FOUT == 4 * L, "mapping assumes FOUT = 2*FIN");
    __shared__ alignas(16) float Ws[FIN * FOUT];
    __shared__ float bs[FOUT];
    for (int i = threadIdx.x; i < FIN * FOUT; i += blockDim.x) Ws[i] = W[i];
    for (int i = threadIdx.x; i < FOUT; i += blockDim.x) bs[i] = b[i];
    __syncthreads();
    float a = __ldg(aP);

    int warp = threadIdx.x >> 5, lane = threadIdx.x & 31;
    int sub = lane % L;
    int node = (blockIdx.x * 8 + warp) * NPW + lane / L;
    if (node >= NN) return;

    const float2* __restrict__ hp2 = reinterpret_cast<const float2*>(hp_in_of(LYR));
    float2 acc = __ldg(&hp2[(size_t)node * L + sub]);          // self loop
    int e = __ldg(&g_rowptr[node]);
    int rem = __ldg(&g_deg[node]);
    // unroll-8 for MLP
    for (; rem >= 8; rem -= 8, e += 8) {
        int s[8];
#pragma unroll
        for (int j = 0; j < 8; j++) s[j] = __ldg(g_csr + e + j);
        float2 v[8];
#pragma unroll
        for (int j = 0; j < 8; j++) v[j] = __ldg(&hp2[(size_t)s[j] * L + sub]);
        float sx = 0.f, sy = 0.f;
#pragma unroll
        for (int j = 0; j < 8; j++) { sx += v[j].x; sy += v[j].y; }
        acc.x += sx; acc.y += sy;
    }
    for (; rem >= 2; rem -= 2, e += 2) {
        int s0 = __ldg(g_csr + e), s1 = __ldg(g_csr + e + 1);
        float2 v0 = __ldg(&hp2[(size_t)s0 * L + sub]);
        float2 v1 = __ldg(&hp2[(size_t)s1 * L + sub]);
        acc.x += v0.x + v1.x; acc.y += v0.y + v1.y;
    }
    if (rem) {
        int s = __ldg(g_csr + e);
        float2 v = __ldg(&hp2[(size_t)s * L + sub]);
        acc.x += v.x; acc.y += v.y;
    }
    float dv = __ldg(&g_dinv[node]);
    acc.x *= dv; acc.y *= dv;

    float r0 = bs[4 * sub], r1 = bs[4 * sub + 1];
    float r2 = bs[4 * sub + 2], r3 = bs[4 * sub + 3];
#pragma unroll
    for (int k2 = 0; k2 < L; k2++) {
        float hx = __shfl_sync(0xffffffffu, acc.x, k2, L);
        float hy = __shfl_sync(0xffffffffu, acc.y, k2, L);
        float4 wa = *reinterpret_cast<const float4*>(&Ws[(2 * k2) * FOUT + 4 * sub]);
        float4 wb = *reinterpret_cast<const float4*>(&Ws[(2 * k2 + 1) * FOUT + 4 * sub]);
        r0 += hx * wa.x + hy * wb.x;
        r1 += hx * wa.y + hy * wb.y;
        r2 += hx * wa.z + hy * wb.z;
        r3 += hx * wa.w + hy * wb.w;
    }
    r0 = (r0 >= 0.f) ? r0 : a * r0;
    r1 = (r1 >= 0.f) ? r1 : a * r1;
    r2 = (r2 >= 0.f) ? r2 : a * r2;
    r3 = (r3 >= 0.f) ? r3 : a * r3;

    float* hp_out = hp_out_of(LYR);
    float4 r = make_float4(r0 * dv, r1 * dv, r2 * dv, r3 * dv);
    reinterpret_cast<float4*>(hp_out)[(size_t)node * L + sub] = r;
}

// ---------------- layer 4: pure aggregation into per-graph buckets ----------------
// pooled_pre[g] += dinv[n] * (hp3[n] + sum_{s->n} hp3[s]);  W4/Wlin applied later.
__global__ void __launch_bounds__(256)
k_agg4(const int* __restrict__ batch)
{
    int warp = threadIdx.x >> 5, lane = threadIdx.x & 31;
    int node = blockIdx.x * 8 + warp;
    if (node >= NN) return;

    const float2* __restrict__ hp2 = reinterpret_cast<const float2*>(g_hp3);
    float2 acc = __ldg(&hp2[(size_t)node * 32 + lane]);   // self loop
    int e = __ldg(&g_rowptr[node]);
    int rem = __ldg(&g_deg[node]);
    for (; rem >= 4; rem -= 4, e += 4) {
        int s0 = __ldg(g_csr + e), s1 = __ldg(g_csr + e + 1);
        int s2 = __ldg(g_csr + e + 2), s3 = __ldg(g_csr + e + 3);
        float2 v0 = __ldg(&hp2[(size_t)s0 * 32 + lane]);
        float2 v1 = __ldg(&hp2[(size_t)s1 * 32 + lane]);
        float2 v2 = __ldg(&hp2[(size_t)s2 * 32 + lane]);
        float2 v3 = __ldg(&hp2[(size_t)s3 * 32 + lane]);
        acc.x += (v0.x + v1.x) + (v2.x + v3.x);
        acc.y += (v0.y + v1.y) + (v2.y + v3.y);
    }
    for (; rem > 0; rem--, e++) {
        int s = __ldg(g_csr + e);
        float2 v = __ldg(&hp2[(size_t)s * 32 + lane]);
        acc.x += v.x; acc.y += v.y;
    }
    float dv = __ldg(&g_dinv[node]);
    int g = __ldg(&batch[node]);
    red_add_v2(&g_psum[g * 64 + 2 * lane], make_float2(acc.x * dv, acc.y * dv));
}

// ---------------- head: out[g,c] = (psum[g]/cnt[g]) @ Wf + bf ----------------
__global__ void k_final(float* __restrict__ out) {
    int t = threadIdx.x;            // 64 graphs x 4 classes
    int g = t >> 2;
    int cls = t & 3;
    float inv = 1.0f / fmaxf((float)g_pcnt[g], 1.0f);
    float acc = g_bf[cls];
#pragma unroll 8
    for (int k = 0; k < 64; k++)
        acc += g_psum[g * 64 + k] * inv * g_Wf[k * 4 + cls];
    out[g * 4 + cls] = acc;
}

// ---------------- launch ----------------
extern "C" void kernel_launch(void* const* d_in, const int* in_sizes, int n_in,
                              void* d_out, int out_size) {
    const float* x    = (const float*)d_in[0];
    const int*   es   = (const int*)d_in[1];
    const int*   ed   = (const int*)d_in[2];
    const int*   bt   = (const int*)d_in[3];
    const float* W1   = (const float*)d_in[4];
    const float* b1   = (const float*)d_in[5];
    const float* W2   = (const float*)d_in[6];
    const float* b2   = (const float*)d_in[7];
    const float* W3   = (const float*)d_in[8];
    const float* b3   = (const float*)d_in[9];
    const float* W4   = (const float*)d_in[10];
    const float* b4   = (const float*)d_in[11];
    const float* a1   = (const float*)d_in[12];
    const float* a2   = (const float*)d_in[13];
    const float* a3   = (const float*)d_in[14];
    const float* Wlin = (const float*)d_in[15];
    const float* blin = (const float*)d_in[16];

    const int B = 256;
    auto gr = [](long long n, int b) { return (unsigned)((n + b - 1) / b); };

    k_zero<<<gr(NN, B), B>>>();
    k_deg_count<<<gr(EE, B), B>>>(ed);
    k_dinv_prep<<<gr(NN, B), B>>>(bt, x);
    k_fusew<<<1, 256>>>(W4, b4, Wlin, blin);
    k_scan1<<<NB, 256>>>();
    k_scan2<<<1, 512>>>();
    k_scan3<<<gr(NN, B), B>>>();
    k_fill<<<gr(EE, B), B>>>(es, ed);

    // layers 1-3: sub-warp mapping (R2), nodes/block = 8 * (32/L)
    k_layer<1, 8, 16><<<gr(NN, 64), B>>>(W1, b1, a1);
    k_layer<2, 16, 32><<<gr(NN, 32), B>>>(W2, b2, a2);
    k_layer<3, 32, 64><<<gr(NN, 16), B>>>(W3, b3, a3);
    // layer 4: aggregation only, fused with pool numerator
    k_agg4<<<gr(NN, 8), B>>>(bt);

    k_final<<<1, 256>>>((float*)d_out);
}

// round 5
// speedup vs baseline: 2.3754x; 1.1415x over previous
#include <cuda_runtime.h>
#include <cuda_bf16.h>

#define NN 100000
#define EE 1600000
#define GG 64
#define NB ((NN + 255) / 256)   // 391 scan blocks

// ---------------- device scratch ----------------
__device__ float g_hp0[NN * 8];
__device__ float g_hp1[NN * 16];
__device__ float g_hp2[NN * 32];
__device__ float4 g_z[NN];          // per-node z = hp3 @ Wf  (layer-3 epilogue)
__device__ int   g_csr[EE];
__device__ int   g_rowptr[NN];
__device__ int   g_cnt[NN];
__device__ int   g_deg[NN];         // in-degree WITHOUT self loop
__device__ float g_dinv[NN];
__device__ float2 g_db[NN];         // {dinv, bitcast(batch)}
__device__ int   g_bsum[NB];
__device__ float g_psum[GG * 4];    // pooled z sums
__device__ int   g_pcnt[GG];
__device__ float g_Wf[64 * 4];      // W4 @ Wlin
__device__ float g_bf[4];           // b4 @ Wlin + blin

// ---------------- init / degree ----------------
__global__ void k_zero() {
    int i = blockIdx.x * blockDim.x + threadIdx.x;
    if (i < NN) g_deg[i] = 0;
    if (i < GG * 4) g_psum[i] = 0.0f;
    if (i < GG) g_pcnt[i] = 0;
}
__global__ void k_deg_count(const int* __restrict__ dst) {
    int e = blockIdx.x * blockDim.x + threadIdx.x;
    if (e < EE) atomicAdd(&g_deg[dst[e]], 1);
}
// dinv + graph counts + prescaled layer-1 features + packed (dinv,batch)
__global__ void k_dinv_prep(const int* __restrict__ batch, const float* __restrict__ x) {
    int n = blockIdx.x * blockDim.x + threadIdx.x;
    if (n >= NN) return;
    float d = rsqrtf((float)(g_deg[n] + 1));
    g_dinv[n] = d;
    int b = batch[n];
    g_db[n] = make_float2(d, __int_as_float(b));
    atomicAdd(&g_pcnt[b], 1);
    float4 v0 = reinterpret_cast<const float4*>(x)[n * 2];
    float4 v1 = reinterpret_cast<const float4*>(x)[n * 2 + 1];
    reinterpret_cast<float4*>(g_hp0)[n * 2] =
        make_float4(v0.x * d, v0.y * d, v0.z * d, v0.w * d);
    reinterpret_cast<float4*>(g_hp0)[n * 2 + 1] =
        make_float4(v1.x * d, v1.y * d, v1.z * d, v1.w * d);
}
// fused head weights: Wf = W4 @ Wlin [64,4], bf = b4 @ Wlin + blin  (parallel)
__global__ void k_fusew(const float* __restrict__ W4, const float* __restrict__ b4,
                        const float* __restrict__ Wlin, const float* __restrict__ blin) {
    int t = threadIdx.x;              // 1024 threads
    int q = t >> 2, p = t & 3;        // q = output 0..255, p = partial 0..3
    int o = q >> 2, c = q & 3;
    float acc = 0.0f;
    const float* w4r = W4 + o * 128 + p * 32;
#pragma unroll 8
    for (int j = 0; j < 32; j++)
        acc += w4r[j] * __ldg(&Wlin[(p * 32 + j) * 4 + c]);
    acc += __shfl_xor_sync(0xffffffffu, acc, 1);
    acc += __shfl_xor_sync(0xffffffffu, acc, 2);
    if (p == 0) g_Wf[o * 4 + c] = acc;
    if (t < 16) {
        int cc = t & 3, pp = t >> 2;
        float bb = 0.0f;
#pragma unroll 8
        for (int j = pp * 32; j < pp * 32 + 32; j++)
            bb += b4[j] * __ldg(&Wlin[j * 4 + cc]);
        bb += __shfl_xor_sync(0x0000ffffu, bb, 4);
        bb += __shfl_xor_sync(0x0000ffffu, bb, 8);
        if (pp == 0) g_bf[cc] = bb + blin[cc];
    }
}

// ---------------- exclusive scan of g_deg -> g_rowptr ----------------
__global__ void k_scan1() {
    int t = threadIdx.x;
    int i = blockIdx.x * 256 + t;
    int v = (i < NN) ? g_deg[i] : 0;
    int lane = t & 31, w = t >> 5;
    int x = v;
#pragma unroll
    for (int d = 1; d < 32; d <<= 1) {
        int y = __shfl_up_sync(0xffffffffu, x, d);
        if (lane >= d) x += y;
    }
    __shared__ int ws[8];
    if (lane == 31) ws[w] = x;
    __syncthreads();
    if (w == 0) {
        int y = (lane < 8) ? ws[lane] : 0;
#pragma unroll
        for (int d = 1; d < 8; d <<= 1) {
            int z = __shfl_up_sync(0xffffffffu, y, d);
            if (lane >= d) y += z;
        }
        if (lane < 8) ws[lane] = y;
    }
    __syncthreads();
    int base = (w > 0) ? ws[w - 1] : 0;
    int incl = base + x;
    if (i < NN) g_rowptr[i] = incl - v;
    if (t == 255) g_bsum[blockIdx.x] = incl;
}
__global__ void k_scan2() {
    int t = threadIdx.x;                       // 512 threads
    int v = (t < NB) ? g_bsum[t] : 0;
    int lane = t & 31, w = t >> 5;
    int x = v;
#pragma unroll
    for (int d = 1; d < 32; d <<= 1) {
        int y = __shfl_up_sync(0xffffffffu, x, d);
        if (lane >= d) x += y;
    }
    __shared__ int ws[16];
    if (lane == 31) ws[w] = x;
    __syncthreads();
    if (w == 0) {
        int y = (lane < 16) ? ws[lane] : 0;
#pragma unroll
        for (int d = 1; d < 16; d <<= 1) {
            int z = __shfl_up_sync(0xffffffffu, y, d);
            if (lane >= d) y += z;
        }
        if (lane < 16) ws[lane] = y;
    }
    __syncthreads();
    int base = (w > 0) ? ws[w - 1] : 0;
    if (t < NB) g_bsum[t] = base + x - v;
}
__global__ void k_scan3() {
    int i = blockIdx.x * blockDim.x + threadIdx.x;
    if (i < NN) {
        int r = g_rowptr[i] + g_bsum[i >> 8];
        g_rowptr[i] = r;
        g_cnt[i] = r;
    }
}
__global__ void k_fill(const int* __restrict__ src, const int* __restrict__ dst) {
    int e = blockIdx.x * blockDim.x + threadIdx.x;
    if (e < EE) {
        int pos = atomicAdd(&g_cnt[dst[e]], 1);
        g_csr[pos] = src[e];
    }
}

// ---------------- fused layers 1-3 ----------------
__device__ __forceinline__ const float* hp_in_of(int layer) {
    switch (layer) { case 1: return g_hp0; case 2: return g_hp1;
                     default: return g_hp2; }
}
__device__ __forceinline__ float* hp_out_of(int layer) {
    switch (layer) { case 1: return g_hp1; default: return g_hp2; }
}

template<int LYR, int FIN, int FOUT>
__global__ void __launch_bounds__(256)
k_layer(const float* __restrict__ W, const float* __restrict__ b,
        const float* __restrict__ aP)
{
    constexpr int L = FIN / 2;            // lanes per node
    constexpr int NPW = 32 / L;           // nodes per warp
    constexpr bool ZOUT = (LYR == 3);     // layer 3 emits z = hp3 @ Wf directly
    static_assert(FOUT == 4 * L, "mapping assumes FOUT = 2*FIN");
    __shared__ alignas(16) float Ws[FIN * FOUT];
    __shared__ float bs[FOUT];
    __shared__ alignas(16) float Wfs[64 * 4];
    for (int i = threadIdx.x; i < FIN * FOUT; i += blockDim.x) Ws[i] = W[i];
    for (int i = threadIdx.x; i < FOUT; i += blockDim.x) bs[i] = b[i];
    if constexpr (ZOUT)
        for (int i = threadIdx.x; i < 256; i += blockDim.x) Wfs[i] = g_Wf[i];
    __syncthreads();
    float a = __ldg(aP);

    int warp = threadIdx.x >> 5, lane = threadIdx.x & 31;
    int sub = lane % L;
    int node = (blockIdx.x * 8 + warp) * NPW + lane / L;
    if (node >= NN) return;

    const float2* __restrict__ hp2 = reinterpret_cast<const float2*>(hp_in_of(LYR));
    float2 acc = __ldg(&hp2[(size_t)node * L + sub]);          // self loop
    int e = __ldg(&g_rowptr[node]);
    int rem = __ldg(&g_deg[node]);
    for (; rem >= 8; rem -= 8, e += 8) {
        int s[8];
#pragma unroll
        for (int j = 0; j < 8; j++) s[j] = __ldg(g_csr + e + j);
        float2 v[8];
#pragma unroll
        for (int j = 0; j < 8; j++) v[j] = __ldg(&hp2[(size_t)s[j] * L + sub]);
        float sx = 0.f, sy = 0.f;
#pragma unroll
        for (int j = 0; j < 8; j++) { sx += v[j].x; sy += v[j].y; }
        acc.x += sx; acc.y += sy;
    }
    for (; rem >= 2; rem -= 2, e += 2) {
        int s0 = __ldg(g_csr + e), s1 = __ldg(g_csr + e + 1);
        float2 v0 = __ldg(&hp2[(size_t)s0 * L + sub]);
        float2 v1 = __ldg(&hp2[(size_t)s1 * L + sub]);
        acc.x += v0.x + v1.x; acc.y += v0.y + v1.y;
    }
    if (rem) {
        int s = __ldg(g_csr + e);
        float2 v = __ldg(&hp2[(size_t)s * L + sub]);
        acc.x += v.x; acc.y += v.y;
    }
    float dv = __ldg(&g_dinv[node]);
    acc.x *= dv; acc.y *= dv;

    float r0 = bs[4 * sub], r1 = bs[4 * sub + 1];
    float r2 = bs[4 * sub + 2], r3 = bs[4 * sub + 3];
#pragma unroll
    for (int k2 = 0; k2 < L; k2++) {
        float hx = __shfl_sync(0xffffffffu, acc.x, k2, L);
        float hy = __shfl_sync(0xffffffffu, acc.y, k2, L);
        float4 wa = *reinterpret_cast<const float4*>(&Ws[(2 * k2) * FOUT + 4 * sub]);
        float4 wb = *reinterpret_cast<const float4*>(&Ws[(2 * k2 + 1) * FOUT + 4 * sub]);
        r0 += hx * wa.x + hy * wb.x;
        r1 += hx * wa.y + hy * wb.y;
        r2 += hx * wa.z + hy * wb.z;
        r3 += hx * wa.w + hy * wb.w;
    }
    r0 = (r0 >= 0.f) ? r0 : a * r0;
    r1 = (r1 >= 0.f) ? r1 : a * r1;
    r2 = (r2 >= 0.f) ? r2 : a * r2;
    r3 = (r3 >= 0.f) ? r3 : a * r3;

    if constexpr (ZOUT) {
        // z[node][c] = dv * sum_i r_i * Wf[(4*sub+i)][c], reduced over 16 lanes
        float4 w0 = *reinterpret_cast<const float4*>(&Wfs[(4 * sub + 0) * 4]);
        float4 w1 = *reinterpret_cast<const float4*>(&Wfs[(4 * sub + 1) * 4]);
        float4 w2 = *reinterpret_cast<const float4*>(&Wfs[(4 * sub + 2) * 4]);
        float4 w3 = *reinterpret_cast<const float4*>(&Wfs[(4 * sub + 3) * 4]);
        float pz0 = dv * (r0 * w0.x + r1 * w1.x + r2 * w2.x + r3 * w3.x);
        float pz1 = dv * (r0 * w0.y + r1 * w1.y + r2 * w2.y + r3 * w3.y);
        float pz2 = dv * (r0 * w0.z + r1 * w1.z + r2 * w2.z + r3 * w3.z);
        float pz3 = dv * (r0 * w0.w + r1 * w1.w + r2 * w2.w + r3 * w3.w);
#pragma unroll
        for (int off = 1; off < 16; off <<= 1) {
            pz0 += __shfl_xor_sync(0xffffffffu, pz0, off);
            pz1 += __shfl_xor_sync(0xffffffffu, pz1, off);
            pz2 += __shfl_xor_sync(0xffffffffu, pz2, off);
            pz3 += __shfl_xor_sync(0xffffffffu, pz3, off);
        }
        if (sub == 0) g_z[node] = make_float4(pz0, pz1, pz2, pz3);
    } else {
        float* hp_out = hp_out_of(LYR);
        float4 r = make_float4(r0 * dv, r1 * dv, r2 * dv, r3 * dv);
        reinterpret_cast<float4*>(hp_out)[(size_t)node * L + sub] = r;
    }
}

// ---------------- pooled layer-4: edge-parallel over z (16 B per edge) ----------
#define PG 1184
__global__ void __launch_bounds__(256)
k_pool4(const int* __restrict__ src, const int* __restrict__ dst)
{
    __shared__ float acc[GG * 4];
    acc[threadIdx.x] = 0.0f;        // blockDim == 256 == GG*4
    __syncthreads();
    const long long T = (long long)EE + NN;
    for (long long t = (long long)blockIdx.x * blockDim.x + threadIdx.x;
         t < T; t += (long long)PG * 256) {
        int s, d;
        if (t < EE) { s = __ldg(src + t); d = __ldg(dst + t); }
        else        { s = d = (int)(t - EE); }
        float2 db = __ldg(&g_db[d]);
        float w = db.x;
        int g = __float_as_int(db.y);
        float4 z = __ldg(&g_z[s]);
        atomicAdd(&acc[g * 4 + 0], w * z.x);
        atomicAdd(&acc[g * 4 + 1], w * z.y);
        atomicAdd(&acc[g * 4 + 2], w * z.z);
        atomicAdd(&acc[g * 4 + 3], w * z.w);
    }
    __syncthreads();
    float v = acc[threadIdx.x];
    if (v != 0.0f) atomicAdd(&g_psum[threadIdx.x], v);
}

// ---------------- head ----------------
__global__ void k_final(float* __restrict__ out) {
    int t = threadIdx.x;            // 64 graphs x 4 classes
    int g = t >> 2;
    int cls = t & 3;
    float inv = 1.0f / fmaxf((float)g_pcnt[g], 1.0f);
    out[g * 4 + cls] = g_psum[g * 4 + cls] * inv + g_bf[cls];
}

// ---------------- launch ----------------
extern "C" void kernel_launch(void* const* d_in, const int* in_sizes, int n_in,
                              void* d_out, int out_size) {
    const float* x    = (const float*)d_in[0];
    const int*   es   = (const int*)d_in[1];
    const int*   ed   = (const int*)d_in[2];
    const int*   bt   = (const int*)d_in[3];
    const float* W1   = (const float*)d_in[4];
    const float* b1   = (const float*)d_in[5];
    const float* W2   = (const float*)d_in[6];
    const float* b2   = (const float*)d_in[7];
    const float* W3   = (const float*)d_in[8];
    const float* b3   = (const float*)d_in[9];
    const float* W4   = (const float*)d_in[10];
    const float* b4   = (const float*)d_in[11];
    const float* a1   = (const float*)d_in[12];
    const float* a2   = (const float*)d_in[13];
    const float* a3   = (const float*)d_in[14];
    const float* Wlin = (const float*)d_in[15];
    const float* blin = (const float*)d_in[16];

    const int B = 256;
    auto gr = [](long long n, int b) { return (unsigned)((n + b - 1) / b); };

    k_zero<<<gr(NN, B), B>>>();
    k_deg_count<<<gr(EE, B), B>>>(ed);
    k_dinv_prep<<<gr(NN, B), B>>>(bt, x);
    k_fusew<<<1, 1024>>>(W4, b4, Wlin, blin);
    k_scan1<<<NB, 256>>>();
    k_scan2<<<1, 512>>>();
    k_scan3<<<gr(NN, B), B>>>();
    k_fill<<<gr(EE, B), B>>>(es, ed);

    // layers 1-3: sub-warp mapping, nodes/block = 8 * (32/L)
    k_layer<1, 8, 16><<<gr(NN, 64), B>>>(W1, b1, a1);
    k_layer<2, 16, 32><<<gr(NN, 32), B>>>(W2, b2, a2);
    k_layer<3, 32, 64><<<gr(NN, 16), B>>>(W3, b3, a3);   // emits z directly

    // layer 4 + mean-pool numerator: edge-parallel on z
    k_pool4<<<PG, 256>>>(es, ed);

    k_final<<<1, 256>>>((float*)d_out);
}

// round 7
// speedup vs baseline: 2.5278x; 1.0642x over previous
#include <cuda_runtime.h>
#include <cuda_fp16.h>

#define NN 100000
#define EE 1600000
#define GG 64
#define NB ((NN + 255) / 256)   // 391 scan blocks

// ---------------- device scratch ----------------
__device__ alignas(16) __half2 g_hp0[NN * 4];    // 8 feats as 4 half2
__device__ alignas(16) __half2 g_hp1[NN * 8];    // 16 feats
__device__ alignas(16) __half2 g_hp2[NN * 16];   // 32 feats
__device__ float4 g_z[NN];          // per-node z = hp3 @ Wf (layer-3 epilogue)
__device__ int   g_csr[EE];
__device__ int   g_rowptr[NN];      // block-local exclusive (add g_bsum[n>>8])
__device__ int   g_cnt[NN];
__device__ int   g_deg[NN];         // in-degree WITHOUT self loop
__device__ float g_dinv[NN];
__device__ float2 g_db[NN];         // {dinv, bitcast(batch)}
__device__ int   g_bsum[NB];
__device__ float g_psum[GG * 4];
__device__ int   g_pcnt[GG];
__device__ float g_Wf[64 * 4];      // W4 @ Wlin
__device__ float g_bf[4];           // b4 @ Wlin + blin

__device__ __forceinline__ unsigned h2u(__half2 h) {
    return *reinterpret_cast<unsigned*>(&h);
}

// ---------------- init / degree ----------------
__global__ void k_zero() {
    int i = blockIdx.x * blockDim.x + threadIdx.x;
    if (i < NN) g_deg[i] = 0;
    if (i < GG * 4) g_psum[i] = 0.0f;
    if (i < GG) g_pcnt[i] = 0;
}
__global__ void k_deg_count(const int* __restrict__ dst) {
    int e = blockIdx.x * blockDim.x + threadIdx.x;
    if (e < EE) atomicAdd(&g_deg[dst[e]], 1);
}
// dinv + graph counts + prescaled fp16 layer-1 features + fused head weights
__global__ void k_dinv_prep(const int* __restrict__ batch, const float* __restrict__ x,
                            const float* __restrict__ W4, const float* __restrict__ b4,
                            const float* __restrict__ Wlin, const float* __restrict__ blin) {
    int n = blockIdx.x * blockDim.x + threadIdx.x;
    if (n < NN) {
        float d = rsqrtf((float)(g_deg[n] + 1));
        g_dinv[n] = d;
        int b = batch[n];
        g_db[n] = make_float2(d, __int_as_float(b));
        atomicAdd(&g_pcnt[b], 1);
        float4 v0 = reinterpret_cast<const float4*>(x)[n * 2];
        float4 v1 = reinterpret_cast<const float4*>(x)[n * 2 + 1];
        __half2 h0 = __floats2half2_rn(v0.x * d, v0.y * d);
        __half2 h1 = __floats2half2_rn(v0.z * d, v0.w * d);
        __half2 h2 = __floats2half2_rn(v1.x * d, v1.y * d);
        __half2 h3 = __floats2half2_rn(v1.z * d, v1.w * d);
        uint4 pk = make_uint4(h2u(h0), h2u(h1), h2u(h2), h2u(h3));
        reinterpret_cast<uint4*>(g_hp0)[n] = pk;
    }
    // block 0: fold head weights Wf = W4 @ Wlin, bf = b4 @ Wlin + blin
    if (blockIdx.x == 0) {
        int t = threadIdx.x;           // 256 = 64 rows x 4 cols
        int o = t >> 2, c = t & 3;
        float acc = 0.0f;
#pragma unroll 16
        for (int j = 0; j < 128; j++)
            acc += __ldg(&W4[o * 128 + j]) * __ldg(&Wlin[j * 4 + c]);
        g_Wf[o * 4 + c] = acc;
        if (t < 4) {
            float bb = blin[t];
            for (int j = 0; j < 128; j++) bb += b4[j] * __ldg(&Wlin[j * 4 + t]);
            g_bf[t] = bb;
        }
    }
}

// ---------------- scan: block-local exclusive + block sums ----------------
__global__ void k_scan1() {
    int t = threadIdx.x;
    int i = blockIdx.x * 256 + t;
    int v = (i < NN) ? g_deg[i] : 0;
    int lane = t & 31, w = t >> 5;
    int x = v;
#pragma unroll
    for (int d = 1; d < 32; d <<= 1) {
        int y = __shfl_up_sync(0xffffffffu, x, d);
        if (lane >= d) x += y;
    }
    __shared__ int ws[8];
    if (lane == 31) ws[w] = x;
    __syncthreads();
    if (w == 0) {
        int y = (lane < 8) ? ws[lane] : 0;
#pragma unroll
        for (int d = 1; d < 8; d <<= 1) {
            int z = __shfl_up_sync(0xffffffffu, y, d);
            if (lane >= d) y += z;
        }
        if (lane < 8) ws[lane] = y;
    }
    __syncthreads();
    int base = (w > 0) ? ws[w - 1] : 0;
    int incl = base + x;
    if (i < NN) {
        int ex = incl - v;
        g_rowptr[i] = ex;
        g_cnt[i] = ex;
    }
    if (t == 255) g_bsum[blockIdx.x] = incl;
}
__global__ void k_scan2() {
    int t = threadIdx.x;                       // 512 threads
    int v = (t < NB) ? g_bsum[t] : 0;
    int lane = t & 31, w = t >> 5;
    int x = v;
#pragma unroll
    for (int d = 1; d < 32; d <<= 1) {
        int y = __shfl_up_sync(0xffffffffu, x, d);
        if (lane >= d) x += y;
    }
    __shared__ int ws[16];
    if (lane == 31) ws[w] = x;
    __syncthreads();
    if (w == 0) {
        int y = (lane < 16) ? ws[lane] : 0;
#pragma unroll
        for (int d = 1; d < 16; d <<= 1) {
            int z = __shfl_up_sync(0xffffffffu, y, d);
            if (lane >= d) y += z;
        }
        if (lane < 16) ws[lane] = y;
    }
    __syncthreads();
    int base = (w > 0) ? ws[w - 1] : 0;
    if (t < NB) g_bsum[t] = base + x - v;
}
__global__ void k_fill(const int* __restrict__ src, const int* __restrict__ dst) {
    int e = blockIdx.x * blockDim.x + threadIdx.x;
    if (e < EE) {
        int d = dst[e];
        int pos = atomicAdd(&g_cnt[d], 1) + __ldg(&g_bsum[d >> 8]);
        g_csr[pos] = src[e];
    }
}

// ---------------- fused layers 1-3 (fp16 features, fp32 math) ----------------
__device__ __forceinline__ const __half2* hp_in_of(int layer) {
    switch (layer) { case 1: return g_hp0; case 2: return g_hp1;
                     default: return g_hp2; }
}
__device__ __forceinline__ __half2* hp_out_of(int layer) {
    switch (layer) { case 1: return g_hp1; default: return g_hp2; }
}

template<int LYR, int FIN, int FOUT>
__global__ void __launch_bounds__(256)
k_layer(const float* __restrict__ W, const float* __restrict__ b,
        const float* __restrict__ aP)
{
    constexpr int L = FIN / 2;            // half2 lanes per node
    constexpr int NPW = 32 / L;           // nodes per warp
    constexpr bool ZOUT = (LYR == 3);
    static_assert(FOUT == 4 * L, "mapping assumes FOUT = 2*FIN");
    __shared__ alignas(16) float Ws[FIN * FOUT];
    __shared__ float bs[FOUT];
    __shared__ alignas(16) float Wfs[64 * 4];
    for (int i = threadIdx.x; i < FIN * FOUT; i += blockDim.x) Ws[i] = W[i];
    for (int i = threadIdx.x; i < FOUT; i += blockDim.x) bs[i] = b[i];
    if constexpr (ZOUT)
        for (int i = threadIdx.x; i < 256; i += blockDim.x) Wfs[i] = g_Wf[i];
    __syncthreads();
    float a = __ldg(aP);

    int warp = threadIdx.x >> 5, lane = threadIdx.x & 31;
    int sub = lane % L;
    int node = (blockIdx.x * 8 + warp) * NPW + lane / L;
    if (node >= NN) return;

    const __half2* __restrict__ hp = hp_in_of(LYR);
    float2 acc = __half22float2(__ldg(&hp[(size_t)node * L + sub]));  // self loop
    int e = __ldg(&g_rowptr[node]) + __ldg(&g_bsum[node >> 8]);
    int rem = __ldg(&g_deg[node]);
    for (; rem >= 8; rem -= 8, e += 8) {
        int s[8];
#pragma unroll
        for (int j = 0; j < 8; j++) s[j] = __ldg(g_csr + e + j);
        __half2 v[8];
#pragma unroll
        for (int j = 0; j < 8; j++) v[j] = __ldg(&hp[(size_t)s[j] * L + sub]);
        float sx = 0.f, sy = 0.f;
#pragma unroll
        for (int j = 0; j < 8; j++) {
            float2 f = __half22float2(v[j]);
            sx += f.x; sy += f.y;
        }
        acc.x += sx; acc.y += sy;
    }
    for (; rem >= 2; rem -= 2, e += 2) {
        int s0 = __ldg(g_csr + e), s1 = __ldg(g_csr + e + 1);
        float2 v0 = __half22float2(__ldg(&hp[(size_t)s0 * L + sub]));
        float2 v1 = __half22float2(__ldg(&hp[(size_t)s1 * L + sub]));
        acc.x += v0.x + v1.x; acc.y += v0.y + v1.y;
    }
    if (rem) {
        int s = __ldg(g_csr + e);
        float2 v = __half22float2(__ldg(&hp[(size_t)s * L + sub]));
        acc.x += v.x; acc.y += v.y;
    }
    float dv = __ldg(&g_dinv[node]);
    acc.x *= dv; acc.y *= dv;

    float r0 = bs[4 * sub], r1 = bs[4 * sub + 1];
    float r2 = bs[4 * sub + 2], r3 = bs[4 * sub + 3];
#pragma unroll
    for (int k2 = 0; k2 < L; k2++) {
        float hx = __shfl_sync(0xffffffffu, acc.x, k2, L);
        float hy = __shfl_sync(0xffffffffu, acc.y, k2, L);
        float4 wa = *reinterpret_cast<const float4*>(&Ws[(2 * k2) * FOUT + 4 * sub]);
        float4 wb = *reinterpret_cast<const float4*>(&Ws[(2 * k2 + 1) * FOUT + 4 * sub]);
        r0 += hx * wa.x + hy * wb.x;
        r1 += hx * wa.y + hy * wb.y;
        r2 += hx * wa.z + hy * wb.z;
        r3 += hx * wa.w + hy * wb.w;
    }
    r0 = (r0 >= 0.f) ? r0 : a * r0;
    r1 = (r1 >= 0.f) ? r1 : a * r1;
    r2 = (r2 >= 0.f) ? r2 : a * r2;
    r3 = (r3 >= 0.f) ? r3 : a * r3;

    if constexpr (ZOUT) {
        float4 w0 = *reinterpret_cast<const float4*>(&Wfs[(4 * sub + 0) * 4]);
        float4 w1 = *reinterpret_cast<const float4*>(&Wfs[(4 * sub + 1) * 4]);
        float4 w2 = *reinterpret_cast<const float4*>(&Wfs[(4 * sub + 2) * 4]);
        float4 w3 = *reinterpret_cast<const float4*>(&Wfs[(4 * sub + 3) * 4]);
        float pz0 = dv * (r0 * w0.x + r1 * w1.x + r2 * w2.x + r3 * w3.x);
        float pz1 = dv * (r0 * w0.y + r1 * w1.y + r2 * w2.y + r3 * w3.y);
        float pz2 = dv * (r0 * w0.z + r1 * w1.z + r2 * w2.z + r3 * w3.z);
        float pz3 = dv * (r0 * w0.w + r1 * w1.w + r2 * w2.w + r3 * w3.w);
#pragma unroll
        for (int off = 1; off < 16; off <<= 1) {
            pz0 += __shfl_xor_sync(0xffffffffu, pz0, off);
            pz1 += __shfl_xor_sync(0xffffffffu, pz1, off);
            pz2 += __shfl_xor_sync(0xffffffffu, pz2, off);
            pz3 += __shfl_xor_sync(0xffffffffu, pz3, off);
        }
        if (sub == 0) g_z[node] = make_float4(pz0, pz1, pz2, pz3);
    } else {
        __half2* hp_out = hp_out_of(LYR);
        __half2 o0 = __floats2half2_rn(r0 * dv, r1 * dv);
        __half2 o1 = __floats2half2_rn(r2 * dv, r3 * dv);
        uint2 pk = make_uint2(h2u(o0), h2u(o1));
        reinterpret_cast<uint2*>(hp_out)[(size_t)node * L + sub] = pk;
    }
}

// ---------------- pooled layer-4: edge-parallel over z (16 B per edge) ----------
#define PG 1184
__global__ void __launch_bounds__(256)
k_pool4(const int* __restrict__ src, const int* __restrict__ dst)
{
    __shared__ float acc[GG * 4];
    acc[threadIdx.x] = 0.0f;        // blockDim == 256 == GG*4
    __syncthreads();
    const long long T = (long long)EE + NN;
    for (long long t = (long long)blockIdx.x * blockDim.x + threadIdx.x;
         t < T; t += (long long)PG * 256) {
        int s, d;
        if (t < EE) { s = __ldg(src + t); d = __ldg(dst + t); }
        else        { s = d = (int)(t - EE); }
        float2 db = __ldg(&g_db[d]);
        float w = db.x;
        int g = __float_as_int(db.y);
        float4 z = __ldg(&g_z[s]);
        atomicAdd(&acc[g * 4 + 0], w * z.x);
        atomicAdd(&acc[g * 4 + 1], w * z.y);
        atomicAdd(&acc[g * 4 + 2], w * z.z);
        atomicAdd(&acc[g * 4 + 3], w * z.w);
    }
    __syncthreads();
    float v = acc[threadIdx.x];
    if (v != 0.0f) atomicAdd(&g_psum[threadIdx.x], v);
}

// ---------------- head ----------------
__global__ void k_final(float* __restrict__ out) {
    int t = threadIdx.x;            // 64 graphs x 4 classes
    int g = t >> 2;
    int cls = t & 3;
    float inv = 1.0f / fmaxf((float)g_pcnt[g], 1.0f);
    out[g * 4 + cls] = g_psum[g * 4 + cls] * inv + g_bf[cls];
}

// ---------------- launch ----------------
extern "C" void kernel_launch(void* const* d_in, const int* in_sizes, int n_in,
                              void* d_out, int out_size) {
    const float* x    = (const float*)d_in[0];
    const int*   es   = (const int*)d_in[1];
    const int*   ed   = (const int*)d_in[2];
    const int*   bt   = (const int*)d_in[3];
    const float* W1   = (const float*)d_in[4];
    const float* b1   = (const float*)d_in[5];
    const float* W2   = (const float*)d_in[6];
    const float* b2   = (const float*)d_in[7];
    const float* W3   = (const float*)d_in[8];
    const float* b3   = (const float*)d_in[9];
    const float* W4   = (const float*)d_in[10];
    const float* b4   = (const float*)d_in[11];
    const float* a1   = (const float*)d_in[12];
    const float* a2   = (const float*)d_in[13];
    const float* a3   = (const float*)d_in[14];
    const float* Wlin = (const float*)d_in[15];
    const float* blin = (const float*)d_in[16];

    const int B = 256;
    auto gr = [](long long n, int b) { return (unsigned)((n + b - 1) / b); };

    k_zero<<<gr(NN, B), B>>>();
    k_deg_count<<<gr(EE, B), B>>>(ed);
    k_dinv_prep<<<gr(NN, B), B>>>(bt, x, W4, b4, Wlin, blin);
    k_scan1<<<NB, 256>>>();
    k_scan2<<<1, 512>>>();
    k_fill<<<gr(EE, B), B>>>(es, ed);

    // layers 1-3: sub-warp mapping, nodes/block = 8 * (32/L)
    k_layer<1, 8, 16><<<gr(NN, 64), B>>>(W1, b1, a1);
    k_layer<2, 16, 32><<<gr(NN, 32), B>>>(W2, b2, a2);
    k_layer<3, 32, 64><<<gr(NN, 16), B>>>(W3, b3, a3);   // emits z directly

    // layer 4 + mean-pool numerator: edge-parallel on z
    k_pool4<<<PG, 256>>>(es, ed);

    k_final<<<1, 256>>>((float*)d_out);
}